// round 1
// baseline (speedup 1.0000x reference)
#include <cuda_runtime.h>
#include <math.h>

#define BB 8
#define SS 2048
#define DD 256
#define RR (BB*SS)          // 16384 rows total
#define NT (SS/64)          // 32 tiles of 64 along S
#define NEG_INF -1.0e30f

// ---------------- static scratch (no allocations allowed) ----------------
__device__ float    g_nrm[(size_t)RR*DD];            // 16 MB
__device__ float    g_sim[(size_t)BB*SS*SS];         // 134 MB
__device__ int      g_top[(size_t)RR*3];
__device__ unsigned g_mask[(size_t)RR*(SS/32)];      // 4 MB bitset adjacency
__device__ float    g_nm[(size_t)RR*DD];             // neighbor mean, 16 MB
__device__ float    g_y[(size_t)RR*DD];              // pre-LN y, 16 MB

// ---------------- 1. row L2-normalize ----------------
__global__ void k_norm(const float* __restrict__ x) {
    int row = blockIdx.x;
    int t = threadIdx.x;
    float v = x[(size_t)row*DD + t];
    __shared__ float sh[8];
    float s = v*v;
    #pragma unroll
    for (int o = 16; o > 0; o >>= 1) s += __shfl_xor_sync(0xffffffffu, s, o);
    if ((t & 31) == 0) sh[t >> 5] = s;
    __syncthreads();
    if (t < 32) {
        float z = (t < 8) ? sh[t] : 0.f;
        #pragma unroll
        for (int o = 4; o > 0; o >>= 1) z += __shfl_xor_sync(0xffffffffu, z, o);
        if (t == 0) sh[0] = z;
    }
    __syncthreads();
    float nrm = sqrtf(sh[0]);
    float sc = 1.f / fmaxf(nrm, 1e-12f);
    g_nrm[(size_t)row*DD + t] = v * sc;
}

// ---------------- 2. sim = nrm @ nrm^T (triangular blocks, mirrored write) ----------------
// grid: (NT*(NT+1)/2, B), block 256 threads, 64x64 tile, 4x4 per thread
__global__ void k_sim() {
    int t = blockIdx.x;
    int bi = (int)((sqrtf(8.f*(float)t + 1.f) - 1.f) * 0.5f);
    while ((bi+1)*(bi+2)/2 <= t) bi++;
    while (bi*(bi+1)/2 > t) bi--;
    int bj = t - bi*(bi+1)/2;     // bi >= bj
    int b = blockIdx.y;

    const float* base = g_nrm + (size_t)b*SS*DD;
    int rA = bi*64, rB = bj*64;

    __shared__ float As[16][64];
    __shared__ float Bs[16][64];
    __shared__ float Cs[64][65];   // transposed tile for coalesced mirror writes

    int tid = threadIdx.x;
    int tx = tid & 15, ty = tid >> 4;
    int lm = tid >> 2;             // 0..63
    int lk = (tid & 3) * 4;        // 0,4,8,12

    float acc[4][4] = {};

    for (int kk = 0; kk < DD; kk += 16) {
        float4 a  = *(const float4*)(base + (size_t)(rA+lm)*DD + kk + lk);
        float4 bv = *(const float4*)(base + (size_t)(rB+lm)*DD + kk + lk);
        As[lk+0][lm] = a.x;  As[lk+1][lm] = a.y;  As[lk+2][lm] = a.z;  As[lk+3][lm] = a.w;
        Bs[lk+0][lm] = bv.x; Bs[lk+1][lm] = bv.y; Bs[lk+2][lm] = bv.z; Bs[lk+3][lm] = bv.w;
        __syncthreads();
        #pragma unroll
        for (int k = 0; k < 16; k++) {
            float av[4], bw[4];
            #pragma unroll
            for (int i = 0; i < 4; i++) av[i] = As[k][ty*4 + i];
            #pragma unroll
            for (int j = 0; j < 4; j++) bw[j] = Bs[k][tx*4 + j];
            #pragma unroll
            for (int i = 0; i < 4; i++)
                #pragma unroll
                for (int j = 0; j < 4; j++)
                    acc[i][j] += av[i] * bw[j];
        }
        __syncthreads();
    }

    float* simb = g_sim + (size_t)b*SS*SS;
    // direct (row-major) write + stage transpose in smem
    #pragma unroll
    for (int i = 0; i < 4; i++) {
        int gi = rA + ty*4 + i;
        #pragma unroll
        for (int j = 0; j < 4; j++) {
            int gj = rB + tx*4 + j;
            simb[(size_t)gi*SS + gj] = acc[i][j];
            Cs[tx*4 + j][ty*4 + i] = acc[i][j];
        }
    }
    __syncthreads();
    // mirror write, coalesced rows
    for (int w = tid; w < 64*64; w += 256) {
        int n = w >> 6, m = w & 63;
        simb[(size_t)(rB + n)*SS + rA + m] = Cs[n][m];
    }
}

// ---------------- 3. top-3 per row (excluding diagonal) ----------------
__global__ void k_top3() {
    int row = blockIdx.x;
    int b = row / SS, i = row % SS;
    const float* srow = g_sim + (size_t)b*SS*SS + (size_t)i*SS;
    __shared__ float sv[SS];
    __shared__ float rv[256];
    __shared__ int   ri[256];
    int t = threadIdx.x;
    #pragma unroll
    for (int q = 0; q < 8; q++) {
        int idx = q*256 + t;
        sv[idx] = (idx == i) ? NEG_INF : srow[idx];
    }
    __syncthreads();
    for (int p = 0; p < 3; p++) {
        float bv = NEG_INF; int bidx = SS;
        #pragma unroll
        for (int q = 0; q < 8; q++) {
            int idx = q*256 + t;
            float v = sv[idx];
            if (v > bv || (v == bv && idx < bidx)) { bv = v; bidx = idx; }
        }
        rv[t] = bv; ri[t] = bidx;
        __syncthreads();
        for (int o = 128; o > 0; o >>= 1) {
            if (t < o) {
                float v2 = rv[t+o]; int i2 = ri[t+o];
                if (v2 > rv[t] || (v2 == rv[t] && i2 < ri[t])) { rv[t] = v2; ri[t] = i2; }
            }
            __syncthreads();
        }
        int win = ri[0];
        if (t == 0) {
            g_top[(size_t)row*3 + p] = win;
            sv[win] = NEG_INF;
        }
        __syncthreads();
    }
}

// ---------------- 4. adjacency bitmask ----------------
__global__ void k_zmask() {
    int t = blockIdx.x*256 + threadIdx.x;
    if (t < RR*(SS/32)) g_mask[t] = 0u;
}

__global__ void k_edges() {
    int t = blockIdx.x*256 + threadIdx.x;
    if (t >= RR*3) return;
    int row = t / 3;
    int j = g_top[t];
    int b = row / SS, i = row % SS;
    atomicOr(&g_mask[(size_t)row*(SS/32) + (j >> 5)], 1u << (j & 31));
    atomicOr(&g_mask[((size_t)b*SS + j)*(SS/32) + (i >> 5)], 1u << (i & 31));
}

// ---------------- 5. neighbor aggregation ----------------
__global__ void k_agg(const float* __restrict__ x) {
    int row = blockIdx.x;
    int b = row / SS, i = row % SS;
    __shared__ int   sj[256];
    __shared__ float sw[256];
    __shared__ int   cnt;
    int t = threadIdx.x;
    if (t == 0) cnt = 0;
    __syncthreads();
    if (t < SS/32) {
        unsigned w = g_mask[(size_t)row*(SS/32) + t];
        while (w) {
            int bpos = __ffs(w) - 1;
            w &= w - 1;
            int j = t*32 + bpos;
            int p = atomicAdd(&cnt, 1);
            if (p < 256) {
                sj[p] = j;
                sw[p] = g_sim[(size_t)b*SS*SS + (size_t)i*SS + j];
            }
        }
    }
    __syncthreads();
    int n = min(cnt, 256);
    float csum = 0.f;
    for (int l = 0; l < n; l++) csum += sw[l];
    float acc = 0.f;
    for (int l = 0; l < n; l++)
        acc += sw[l] * x[((size_t)b*SS + sj[l])*DD + t];
    g_nm[(size_t)row*DD + t] = acc / fmaxf(csum, 1.0f);
}

// ---------------- 6. projection GEMM + bias + residual ----------------
// out[r][d] = x[r][d] + b[d] + sum_f combined[r][f] * W[d][f], combined = [x | nm]
// grid: (R/64)*4 blocks, 64x64 tile, K=512
__global__ void k_out(const float* __restrict__ x, const float* __restrict__ W,
                      const float* __restrict__ bias) {
    int bx = blockIdx.x;
    int rT = bx >> 2, cT = bx & 3;
    int rA = rT*64, cB = cT*64;

    __shared__ float As[16][64];
    __shared__ float Ws[16][64];

    int tid = threadIdx.x;
    int tx = tid & 15, ty = tid >> 4;
    int lm = tid >> 2;
    int lk = (tid & 3) * 4;

    float acc[4][4] = {};

    for (int kk = 0; kk < 2*DD; kk += 16) {
        const float* src = (kk < DD)
            ? (x    + (size_t)(rA+lm)*DD + kk)
            : (g_nm + (size_t)(rA+lm)*DD + (kk - DD));
        float4 a  = *(const float4*)(src + lk);
        float4 w4 = *(const float4*)(W + (size_t)(cB+lm)*(2*DD) + kk + lk);
        As[lk+0][lm] = a.x;  As[lk+1][lm] = a.y;  As[lk+2][lm] = a.z;  As[lk+3][lm] = a.w;
        Ws[lk+0][lm] = w4.x; Ws[lk+1][lm] = w4.y; Ws[lk+2][lm] = w4.z; Ws[lk+3][lm] = w4.w;
        __syncthreads();
        #pragma unroll
        for (int k = 0; k < 16; k++) {
            float av[4], bw[4];
            #pragma unroll
            for (int i = 0; i < 4; i++) av[i] = As[k][ty*4 + i];
            #pragma unroll
            for (int j = 0; j < 4; j++) bw[j] = Ws[k][tx*4 + j];
            #pragma unroll
            for (int i = 0; i < 4; i++)
                #pragma unroll
                for (int j = 0; j < 4; j++)
                    acc[i][j] += av[i] * bw[j];
        }
        __syncthreads();
    }

    #pragma unroll
    for (int i = 0; i < 4; i++) {
        int r = rA + ty*4 + i;
        #pragma unroll
        for (int j = 0; j < 4; j++) {
            int d = cB + tx*4 + j;
            g_y[(size_t)r*DD + d] = x[(size_t)r*DD + d] + acc[i][j] + bias[d];
        }
    }
}

// ---------------- 7. LayerNorm ----------------
__global__ void k_ln(const float* __restrict__ gamma, const float* __restrict__ beta,
                     float* __restrict__ out) {
    int row = blockIdx.x;
    int t = threadIdx.x;
    float v = g_y[(size_t)row*DD + t];
    __shared__ float sh[8];

    float s = v;
    #pragma unroll
    for (int o = 16; o > 0; o >>= 1) s += __shfl_xor_sync(0xffffffffu, s, o);
    if ((t & 31) == 0) sh[t >> 5] = s;
    __syncthreads();
    if (t < 32) {
        float z = (t < 8) ? sh[t] : 0.f;
        #pragma unroll
        for (int o = 4; o > 0; o >>= 1) z += __shfl_xor_sync(0xffffffffu, z, o);
        if (t == 0) sh[0] = z;
    }
    __syncthreads();
    float mu = sh[0] * (1.0f/DD);
    __syncthreads();

    float d = v - mu;
    float s2 = d*d;
    #pragma unroll
    for (int o = 16; o > 0; o >>= 1) s2 += __shfl_xor_sync(0xffffffffu, s2, o);
    if ((t & 31) == 0) sh[t >> 5] = s2;
    __syncthreads();
    if (t < 32) {
        float z = (t < 8) ? sh[t] : 0.f;
        #pragma unroll
        for (int o = 4; o > 0; o >>= 1) z += __shfl_xor_sync(0xffffffffu, z, o);
        if (t == 0) sh[0] = z;
    }
    __syncthreads();
    float var = sh[0] * (1.0f/DD);

    out[(size_t)row*DD + t] = d * rsqrtf(var + 1e-5f) * gamma[t] + beta[t];
}

// ---------------- launch ----------------
extern "C" void kernel_launch(void* const* d_in, const int* in_sizes, int n_in,
                              void* d_out, int out_size) {
    const float* x     = (const float*)d_in[0];
    const float* W     = (const float*)d_in[1];
    const float* bias  = (const float*)d_in[2];
    const float* gamma = (const float*)d_in[3];
    const float* beta  = (const float*)d_in[4];
    float* out = (float*)d_out;

    k_norm<<<RR, 256>>>(x);
    dim3 gs(NT*(NT+1)/2, BB);
    k_sim<<<gs, 256>>>();
    k_top3<<<RR, 256>>>();
    k_zmask<<<(RR*(SS/32) + 255)/256, 256>>>();
    k_edges<<<(RR*3 + 255)/256, 256>>>();
    k_agg<<<RR, 256>>>(x);
    k_out<<<(RR/64)*4, 256>>>(x, W, bias);
    k_ln<<<RR, 256>>>(gamma, beta, out);
}

// round 8
// speedup vs baseline: 1.1444x; 1.1444x over previous
#include <cuda_runtime.h>
#include <cuda_bf16.h>
#include <math.h>
#include <stdint.h>

#define BB 8
#define SS 2048
#define DD 256
#define RR (BB*SS)          // 16384 rows total
#define NEG_INF -1.0e30f

// ----- HMMA sim tiling -----
#define TS2 128
#define NT2 (SS/TS2)                 // 16
#define TRI2 (NT2*(NT2+1)/2)         // 136
#define KC 64
#define NCHUNK (DD/KC)               // 4
#define LDA 72                       // padded smem row stride (bf16 elems)
#define TILE_B (128*LDA*2)           // 18432 bytes per operand tile
#define SIM_SMEM (4*TILE_B)          // 73728 (also covers Cs 128*132*4=67584)

#define NCAND 8

// ---------------- static scratch ----------------
__device__ float    g_nrm[(size_t)RR*DD];            // 16 MB exact normalized rows
__device__ __nv_bfloat16 g_hi[(size_t)RR*DD];        // 8 MB
__device__ __nv_bfloat16 g_lo[(size_t)RR*DD];        // 8 MB
__device__ float    g_sim[(size_t)BB*SS*SS];         // 134 MB (approx, rank-only)
__device__ int      g_top[(size_t)RR*3];
__device__ unsigned g_mask[(size_t)RR*(SS/32)];      // 4 MB
__device__ float    g_nm[(size_t)RR*DD];             // 16 MB
__device__ float    g_y[(size_t)RR*DD];              // 16 MB

__device__ __forceinline__ uint32_t smem_u32(const void* p) {
    uint32_t a;
    asm("{ .reg .u64 t; cvta.to.shared.u64 t, %1; cvt.u32.u64 %0, t; }" : "=r"(a) : "l"(p));
    return a;
}
__device__ __forceinline__ void ldmx4(uint32_t* r, uint32_t addr) {
    asm volatile("ldmatrix.sync.aligned.m8n8.x4.shared.b16 {%0,%1,%2,%3}, [%4];"
        : "=r"(r[0]), "=r"(r[1]), "=r"(r[2]), "=r"(r[3]) : "r"(addr));
}
__device__ __forceinline__ void mma16816(float* c, const uint32_t* a, uint32_t b0, uint32_t b1) {
    asm volatile("mma.sync.aligned.m16n8k16.row.col.f32.bf16.bf16.f32 "
        "{%0,%1,%2,%3}, {%4,%5,%6,%7}, {%8,%9}, {%0,%1,%2,%3};"
        : "+f"(c[0]), "+f"(c[1]), "+f"(c[2]), "+f"(c[3])
        : "r"(a[0]), "r"(a[1]), "r"(a[2]), "r"(a[3]), "r"(b0), "r"(b1));
}

// ---------------- 1. row L2-normalize -> fp32 + bf16 hi/lo split ----------------
__global__ void k_norm(const float* __restrict__ x) {
    int row = blockIdx.x;
    int t = threadIdx.x;
    float v = x[(size_t)row*DD + t];
    __shared__ float sh[8];
    float s = v*v;
    #pragma unroll
    for (int o = 16; o > 0; o >>= 1) s += __shfl_xor_sync(0xffffffffu, s, o);
    if ((t & 31) == 0) sh[t >> 5] = s;
    __syncthreads();
    if (t < 32) {
        float z = (t < 8) ? sh[t] : 0.f;
        #pragma unroll
        for (int o = 4; o > 0; o >>= 1) z += __shfl_xor_sync(0xffffffffu, z, o);
        if (t == 0) sh[0] = z;
    }
    __syncthreads();
    float nrm = sqrtf(sh[0]);
    float sc = 1.f / fmaxf(nrm, 1e-12f);
    float nv = v * sc;
    __nv_bfloat16 h = __float2bfloat16(nv);
    float lo = nv - __bfloat162float(h);
    g_nrm[(size_t)row*DD + t] = nv;
    g_hi[(size_t)row*DD + t] = h;
    g_lo[(size_t)row*DD + t] = __float2bfloat16(lo);
}

// ---------------- 2. approx sim = nrm @ nrm^T via bf16 HMMA 3-split ----------------
__global__ void __launch_bounds__(256, 2) k_sim3() {
    extern __shared__ char smem[];
    uint32_t sb = smem_u32(smem);
    int tid = threadIdx.x;
    int lane = tid & 31, wid = tid >> 5;
    int wm = wid & 3, wn = wid >> 2;

    int t = blockIdx.x;
    int bi = 0;
    while ((bi+1)*(bi+2)/2 <= t) bi++;
    int bj = t - bi*(bi+1)/2;           // bi >= bj
    int b = blockIdx.y;
    int rA = bi*TS2, rB = bj*TS2;

    const __nv_bfloat16* hib = g_hi + (size_t)b*SS*DD;
    const __nv_bfloat16* lob = g_lo + (size_t)b*SS*DD;

    const uint32_t AH = sb, AL = sb + TILE_B, BH = sb + 2*TILE_B, BL = sb + 3*TILE_B;

    float acc[2][8][4];
    #pragma unroll
    for (int i = 0; i < 2; i++)
        #pragma unroll
        for (int j = 0; j < 8; j++)
            #pragma unroll
            for (int q = 0; q < 4; q++) acc[i][j][q] = 0.f;

    int ar = lane & 15, aseg = lane >> 4;
    int br = lane & 7, bsel = lane >> 3;
    int bnoff = (bsel >> 1) * 8, bkoff = (bsel & 1) * 8;

    int lrow = tid >> 1, lcol = (tid & 1) * 32;

    for (int c = 0; c < NCHUNK; c++) {
        int kk = c * KC;
        {
            const uint4* pAh = (const uint4*)(hib + (size_t)(rA+lrow)*DD + kk + lcol);
            const uint4* pAl = (const uint4*)(lob + (size_t)(rA+lrow)*DD + kk + lcol);
            const uint4* pBh = (const uint4*)(hib + (size_t)(rB+lrow)*DD + kk + lcol);
            const uint4* pBl = (const uint4*)(lob + (size_t)(rB+lrow)*DD + kk + lcol);
            uint32_t so = (uint32_t)(lrow*LDA + lcol) * 2;
            #pragma unroll
            for (int q = 0; q < 4; q++) {
                *(uint4*)(smem + (AH - sb) + so + q*16) = pAh[q];
                *(uint4*)(smem + (AL - sb) + so + q*16) = pAl[q];
                *(uint4*)(smem + (BH - sb) + so + q*16) = pBh[q];
                *(uint4*)(smem + (BL - sb) + so + q*16) = pBl[q];
            }
        }
        __syncthreads();

        #pragma unroll
        for (int ks = 0; ks < KC/16; ks++) {
            int kb = ks * 16;
            uint32_t ah[2][4], al[2][4];
            #pragma unroll
            for (int mt = 0; mt < 2; mt++) {
                uint32_t ao = (uint32_t)((wm*32 + mt*16 + ar)*LDA + kb + aseg*8) * 2;
                ldmx4(ah[mt], AH + ao);
                ldmx4(al[mt], AL + ao);
            }
            #pragma unroll
            for (int np = 0; np < 4; np++) {
                uint32_t bo = (uint32_t)((wn*64 + np*16 + bnoff + br)*LDA + kb + bkoff) * 2;
                uint32_t bh[4], bl[4];
                ldmx4(bh, BH + bo);
                ldmx4(bl, BL + bo);
                #pragma unroll
                for (int mt = 0; mt < 2; mt++) {
                    #pragma unroll
                    for (int sub = 0; sub < 2; sub++) {
                        int nt = np*2 + sub;
                        mma16816(acc[mt][nt], ah[mt], bh[sub*2], bh[sub*2+1]);
                        mma16816(acc[mt][nt], ah[mt], bl[sub*2], bl[sub*2+1]);
                        mma16816(acc[mt][nt], al[mt], bh[sub*2], bh[sub*2+1]);
                    }
                }
            }
        }
        __syncthreads();
    }

    float* simb = g_sim + (size_t)b*SS*SS;
    int fr = lane >> 2, fc = (lane & 3) * 2;

    #pragma unroll
    for (int mt = 0; mt < 2; mt++) {
        #pragma unroll
        for (int nt = 0; nt < 8; nt++) {
            int r0 = rA + wm*32 + mt*16 + fr;
            int cc = rB + wn*64 + nt*8 + fc;
            *(float2*)(simb + (size_t)r0*SS + cc)     = make_float2(acc[mt][nt][0], acc[mt][nt][1]);
            *(float2*)(simb + (size_t)(r0+8)*SS + cc) = make_float2(acc[mt][nt][2], acc[mt][nt][3]);
        }
    }

    if (bi != bj) {
        float* Cs = (float*)smem;   // reuse: [col][row], stride 132
        __syncthreads();
        #pragma unroll
        for (int mt = 0; mt < 2; mt++) {
            #pragma unroll
            for (int nt = 0; nt < 8; nt++) {
                int r0 = wm*32 + mt*16 + fr;
                int cc = wn*64 + nt*8 + fc;
                Cs[(cc+0)*132 + r0]   = acc[mt][nt][0];
                Cs[(cc+1)*132 + r0]   = acc[mt][nt][1];
                Cs[(cc+0)*132 + r0+8] = acc[mt][nt][2];
                Cs[(cc+1)*132 + r0+8] = acc[mt][nt][3];
            }
        }
        __syncthreads();
        for (int w = tid; w < 128*32; w += 256) {
            int n = w >> 5, m4 = (w & 31) * 4;
            float4 v = make_float4(Cs[n*132 + m4], Cs[n*132 + m4 + 1],
                                   Cs[n*132 + m4 + 2], Cs[n*132 + m4 + 3]);
            *(float4*)(simb + (size_t)(rB + n)*SS + rA + m4) = v;
        }
    }
}

// ---------------- 3. top-8 approx candidates -> exact fp32 rescore -> top-3 ----------------
__global__ void k_top3() {
    int row = blockIdx.x;
    int b = row / SS, i = row % SS;
    const float* srow = g_sim + (size_t)b*SS*SS + (size_t)i*SS;
    __shared__ float sv[SS];
    __shared__ float wmax[8];
    __shared__ int   widx[8];
    __shared__ int   cand[NCAND];
    __shared__ float ex[NCAND];
    int t = threadIdx.x;
    int lane = t & 31, wid = t >> 5;

    #pragma unroll
    for (int q = 0; q < 8; q++) {
        int idx = q*256 + t;
        sv[idx] = (idx == i) ? NEG_INF : srow[idx];
    }
    __syncthreads();

    // 8 argmax passes (approx ranking with margin)
    for (int p = 0; p < NCAND; p++) {
        float bv = NEG_INF; int bidx = SS;
        #pragma unroll
        for (int q = 0; q < 8; q++) {
            int idx = q*256 + t;
            float v = sv[idx];
            if (v > bv || (v == bv && idx < bidx)) { bv = v; bidx = idx; }
        }
        #pragma unroll
        for (int o = 16; o > 0; o >>= 1) {
            float ov = __shfl_xor_sync(0xffffffffu, bv, o);
            int   oi = __shfl_xor_sync(0xffffffffu, bidx, o);
            if (ov > bv || (ov == bv && oi < bidx)) { bv = ov; bidx = oi; }
        }
        if (lane == 0) { wmax[wid] = bv; widx[wid] = bidx; }
        __syncthreads();
        if (t < 32) {
            float v2 = (t < 8) ? wmax[t] : NEG_INF;
            int   i2 = (t < 8) ? widx[t] : SS;
            #pragma unroll
            for (int o = 4; o > 0; o >>= 1) {
                float ov = __shfl_xor_sync(0xffffffffu, v2, o);
                int   oi = __shfl_xor_sync(0xffffffffu, i2, o);
                if (ov > v2 || (ov == v2 && oi < i2)) { v2 = ov; i2 = oi; }
            }
            if (t == 0) { cand[p] = i2; sv[i2] = NEG_INF; }
        }
        __syncthreads();
    }

    // exact fp32 rescore of the 8 candidates
    float xi = g_nrm[(size_t)row*DD + t];
    for (int c = 0; c < NCAND; c++) {
        int j = cand[c];
        float pr = xi * g_nrm[((size_t)b*SS + j)*DD + t];
        #pragma unroll
        for (int o = 16; o > 0; o >>= 1) pr += __shfl_xor_sync(0xffffffffu, pr, o);
        if (lane == 0) wmax[wid] = pr;
        __syncthreads();
        if (t < 32) {
            float z = (t < 8) ? wmax[t] : 0.f;
            #pragma unroll
            for (int o = 4; o > 0; o >>= 1) z += __shfl_xor_sync(0xffffffffu, z, o);
            if (t == 0) ex[c] = z;
        }
        __syncthreads();
    }

    if (t == 0) {
        // select top-3 of the 8 exact values (ties -> smaller index)
        bool used[NCAND] = {};
        for (int p = 0; p < 3; p++) {
            float bv = NEG_INF; int bc = -1;
            for (int c = 0; c < NCAND; c++) {
                if (used[c]) continue;
                if (bc < 0 || ex[c] > bv) { bv = ex[c]; bc = c; }
            }
            used[bc] = true;
            g_top[(size_t)row*3 + p] = cand[bc];
        }
    }
}

// ---------------- 4. adjacency bitmask ----------------
__global__ void k_zmask() {
    int t = blockIdx.x*256 + threadIdx.x;
    if (t < RR*(SS/32)) g_mask[t] = 0u;
}

__global__ void k_edges() {
    int t = blockIdx.x*256 + threadIdx.x;
    if (t >= RR*3) return;
    int row = t / 3;
    int j = g_top[t];
    int b = row / SS, i = row % SS;
    atomicOr(&g_mask[(size_t)row*(SS/32) + (j >> 5)], 1u << (j & 31));
    atomicOr(&g_mask[((size_t)b*SS + j)*(SS/32) + (i >> 5)], 1u << (i & 31));
}

// ---------------- 5. neighbor aggregation (exact fp32 weights) ----------------
__global__ void k_agg(const float* __restrict__ x) {
    int row = blockIdx.x;
    int b = row / SS, i = row % SS;
    __shared__ int   sj[128];
    __shared__ float sw[128];
    __shared__ int   cnt;
    int t = threadIdx.x;
    int lane = t & 31, wid = t >> 5;
    if (t == 0) cnt = 0;
    __syncthreads();
    if (t < SS/32) {
        unsigned w = g_mask[(size_t)row*(SS/32) + t];
        while (w) {
            int bpos = __ffs(w) - 1;
            w &= w - 1;
            int j = t*32 + bpos;
            int p = atomicAdd(&cnt, 1);
            if (p < 128) sj[p] = j;
        }
    }
    __syncthreads();
    int n = min(cnt, 128);

    // exact cosine weights: one warp per neighbor
    const float* xi = g_nrm + (size_t)row*DD;
    for (int l = wid; l < n; l += 8) {
        const float* xj = g_nrm + ((size_t)b*SS + sj[l])*DD;
        float s = 0.f;
        #pragma unroll
        for (int q = 0; q < DD/32; q++) s += xi[lane + q*32] * xj[lane + q*32];
        #pragma unroll
        for (int o = 16; o > 0; o >>= 1) s += __shfl_xor_sync(0xffffffffu, s, o);
        if (lane == 0) sw[l] = s;
    }
    __syncthreads();

    float csum = 0.f;
    for (int l = 0; l < n; l++) csum += sw[l];
    float acc = 0.f;
    for (int l = 0; l < n; l++)
        acc += sw[l] * x[((size_t)b*SS + sj[l])*DD + t];
    g_nm[(size_t)row*DD + t] = acc / fmaxf(csum, 1.0f);
}

// ---------------- 6. projection GEMM + bias + residual ----------------
__global__ void k_out(const float* __restrict__ x, const float* __restrict__ W,
                      const float* __restrict__ bias) {
    int bx = blockIdx.x;
    int rT = bx >> 2, cT = bx & 3;
    int rA = rT*64, cB = cT*64;

    __shared__ float As[16][64];
    __shared__ float Ws[16][64];

    int tid = threadIdx.x;
    int tx = tid & 15, ty = tid >> 4;
    int lm = tid >> 2;
    int lk = (tid & 3) * 4;

    float acc[4][4] = {};

    for (int kk = 0; kk < 2*DD; kk += 16) {
        const float* src = (kk < DD)
            ? (x    + (size_t)(rA+lm)*DD + kk)
            : (g_nm + (size_t)(rA+lm)*DD + (kk - DD));
        float4 a  = *(const float4*)(src + lk);
        float4 w4 = *(const float4*)(W + (size_t)(cB+lm)*(2*DD) + kk + lk);
        As[lk+0][lm] = a.x;  As[lk+1][lm] = a.y;  As[lk+2][lm] = a.z;  As[lk+3][lm] = a.w;
        Ws[lk+0][lm] = w4.x; Ws[lk+1][lm] = w4.y; Ws[lk+2][lm] = w4.z; Ws[lk+3][lm] = w4.w;
        __syncthreads();
        #pragma unroll
        for (int k = 0; k < 16; k++) {
            float av[4], bw[4];
            #pragma unroll
            for (int i = 0; i < 4; i++) av[i] = As[k][ty*4 + i];
            #pragma unroll
            for (int j = 0; j < 4; j++) bw[j] = Ws[k][tx*4 + j];
            #pragma unroll
            for (int i = 0; i < 4; i++)
                #pragma unroll
                for (int j = 0; j < 4; j++)
                    acc[i][j] += av[i] * bw[j];
        }
        __syncthreads();
    }

    #pragma unroll
    for (int i = 0; i < 4; i++) {
        int r = rA + ty*4 + i;
        #pragma unroll
        for (int j = 0; j < 4; j++) {
            int d = cB + tx*4 + j;
            g_y[(size_t)r*DD + d] = x[(size_t)r*DD + d] + acc[i][j] + bias[d];
        }
    }
}

// ---------------- 7. LayerNorm ----------------
__global__ void k_ln(const float* __restrict__ gamma, const float* __restrict__ beta,
                     float* __restrict__ out) {
    int row = blockIdx.x;
    int t = threadIdx.x;
    float v = g_y[(size_t)row*DD + t];
    __shared__ float sh[8];

    float s = v;
    #pragma unroll
    for (int o = 16; o > 0; o >>= 1) s += __shfl_xor_sync(0xffffffffu, s, o);
    if ((t & 31) == 0) sh[t >> 5] = s;
    __syncthreads();
    if (t < 32) {
        float z = (t < 8) ? sh[t] : 0.f;
        #pragma unroll
        for (int o = 4; o > 0; o >>= 1) z += __shfl_xor_sync(0xffffffffu, z, o);
        if (t == 0) sh[0] = z;
    }
    __syncthreads();
    float mu = sh[0] * (1.0f/DD);
    __syncthreads();

    float d = v - mu;
    float s2 = d*d;
    #pragma unroll
    for (int o = 16; o > 0; o >>= 1) s2 += __shfl_xor_sync(0xffffffffu, s2, o);
    if ((t & 31) == 0) sh[t >> 5] = s2;
    __syncthreads();
    if (t < 32) {
        float z = (t < 8) ? sh[t] : 0.f;
        #pragma unroll
        for (int o = 4; o > 0; o >>= 1) z += __shfl_xor_sync(0xffffffffu, z, o);
        if (t == 0) sh[0] = z;
    }
    __syncthreads();
    float var = sh[0] * (1.0f/DD);

    out[(size_t)row*DD + t] = d * rsqrtf(var + 1e-5f) * gamma[t] + beta[t];
}

// ---------------- launch ----------------
extern "C" void kernel_launch(void* const* d_in, const int* in_sizes, int n_in,
                              void* d_out, int out_size) {
    const float* x     = (const float*)d_in[0];
    const float* W     = (const float*)d_in[1];
    const float* bias  = (const float*)d_in[2];
    const float* gamma = (const float*)d_in[3];
    const float* beta  = (const float*)d_in[4];
    float* out = (float*)d_out;

    cudaFuncSetAttribute(k_sim3, cudaFuncAttributeMaxDynamicSharedMemorySize, SIM_SMEM);

    k_norm<<<RR, 256>>>(x);
    k_sim3<<<dim3(TRI2, BB), 256, SIM_SMEM>>>();
    k_top3<<<RR, 256>>>();
    k_zmask<<<(RR*(SS/32) + 255)/256, 256>>>();
    k_edges<<<(RR*3 + 255)/256, 256>>>();
    k_agg<<<RR, 256>>>(x);
    k_out<<<(RR/64)*4, 256>>>(x, W, bias);
    k_ln<<<RR, 256>>>(gamma, beta, out);
}

// round 9
// speedup vs baseline: 1.3327x; 1.1645x over previous
#include <cuda_runtime.h>
#include <cuda_bf16.h>
#include <math.h>
#include <stdint.h>

#define BB 8
#define SS 2048
#define DD 256
#define RR (BB*SS)          // 16384 rows total
#define NEG_INF -1.0e30f

// ----- HMMA sim tiling -----
#define TS2 128
#define NT2 (SS/TS2)                 // 16
#define TRI2 (NT2*(NT2+1)/2)         // 136
#define KC 64
#define NCHUNK (DD/KC)               // 4
#define LDA 72                       // padded smem row stride (bf16 elems)
#define TILE_B (128*LDA*2)           // 18432 bytes per operand tile
#define SIM_SMEM (4*TILE_B)          // 73728 (also covers Cs 128*132*4=67584)

#define NCAND 8

// ----- HMMA out tiling -----
#define KF (2*DD)                    // 512
#define OUT_A_B (128*LDA*2)          // 18432
#define OUT_B_B (64*LDA*2)           // 9216
#define OUT_SMEM (2*OUT_A_B + 2*OUT_B_B)   // 55296

// ---------------- static scratch ----------------
__device__ float    g_nrm[(size_t)RR*DD];            // 16 MB exact normalized rows
__device__ __nv_bfloat16 g_hi[(size_t)RR*DD];        // 8 MB
__device__ __nv_bfloat16 g_lo[(size_t)RR*DD];        // 8 MB
__device__ float    g_sim[(size_t)BB*SS*SS];         // 134 MB (approx, rank-only)
__device__ int      g_top[(size_t)RR*3];
__device__ unsigned g_mask[(size_t)RR*(SS/32)];      // 4 MB
__device__ __nv_bfloat16 g_chi[(size_t)RR*KF];       // 16 MB combined hi
__device__ __nv_bfloat16 g_clo[(size_t)RR*KF];       // 16 MB combined lo
__device__ __nv_bfloat16 g_whi[(size_t)DD*KF];       // 256 KB
__device__ __nv_bfloat16 g_wlo[(size_t)DD*KF];       // 256 KB
__device__ float    g_y[(size_t)RR*DD];              // 16 MB

__device__ __forceinline__ uint32_t smem_u32(const void* p) {
    uint32_t a;
    asm("{ .reg .u64 t; cvta.to.shared.u64 t, %1; cvt.u32.u64 %0, t; }" : "=r"(a) : "l"(p));
    return a;
}
__device__ __forceinline__ void ldmx4(uint32_t* r, uint32_t addr) {
    asm volatile("ldmatrix.sync.aligned.m8n8.x4.shared.b16 {%0,%1,%2,%3}, [%4];"
        : "=r"(r[0]), "=r"(r[1]), "=r"(r[2]), "=r"(r[3]) : "r"(addr));
}
__device__ __forceinline__ void mma16816(float* c, const uint32_t* a, uint32_t b0, uint32_t b1) {
    asm volatile("mma.sync.aligned.m16n8k16.row.col.f32.bf16.bf16.f32 "
        "{%0,%1,%2,%3}, {%4,%5,%6,%7}, {%8,%9}, {%0,%1,%2,%3};"
        : "+f"(c[0]), "+f"(c[1]), "+f"(c[2]), "+f"(c[3])
        : "r"(a[0]), "r"(a[1]), "r"(a[2]), "r"(a[3]), "r"(b0), "r"(b1));
}

// ---------------- 1. row L2-normalize -> fp32 + bf16 hi/lo; raw x -> combined[0:256] ----------------
__global__ void k_norm(const float* __restrict__ x) {
    int row = blockIdx.x;
    int t = threadIdx.x;
    float v = x[(size_t)row*DD + t];
    __shared__ float sh[8];
    float s = v*v;
    #pragma unroll
    for (int o = 16; o > 0; o >>= 1) s += __shfl_xor_sync(0xffffffffu, s, o);
    if ((t & 31) == 0) sh[t >> 5] = s;
    __syncthreads();
    if (t < 32) {
        float z = (t < 8) ? sh[t] : 0.f;
        #pragma unroll
        for (int o = 4; o > 0; o >>= 1) z += __shfl_xor_sync(0xffffffffu, z, o);
        if (t == 0) sh[0] = z;
    }
    __syncthreads();
    float nrm = sqrtf(sh[0]);
    float sc = 1.f / fmaxf(nrm, 1e-12f);
    float nv = v * sc;
    __nv_bfloat16 h = __float2bfloat16(nv);
    float lo = nv - __bfloat162float(h);
    g_nrm[(size_t)row*DD + t] = nv;
    g_hi[(size_t)row*DD + t] = h;
    g_lo[(size_t)row*DD + t] = __float2bfloat16(lo);
    // raw x split for the projection GEMM
    __nv_bfloat16 xh = __float2bfloat16(v);
    g_chi[(size_t)row*KF + t] = xh;
    g_clo[(size_t)row*KF + t] = __float2bfloat16(v - __bfloat162float(xh));
}

// ---------------- 1b. W hi/lo split ----------------
__global__ void k_wsplit(const float* __restrict__ W) {
    int t = blockIdx.x*256 + threadIdx.x;   // DD*KF = 131072
    float v = W[t];
    __nv_bfloat16 h = __float2bfloat16(v);
    g_whi[t] = h;
    g_wlo[t] = __float2bfloat16(v - __bfloat162float(h));
}

// ---------------- 2. approx sim = nrm @ nrm^T via bf16 HMMA 3-split ----------------
__global__ void __launch_bounds__(256, 2) k_sim3() {
    extern __shared__ char smem[];
    uint32_t sb = smem_u32(smem);
    int tid = threadIdx.x;
    int lane = tid & 31, wid = tid >> 5;
    int wm = wid & 3, wn = wid >> 2;

    int t = blockIdx.x;
    int bi = 0;
    while ((bi+1)*(bi+2)/2 <= t) bi++;
    int bj = t - bi*(bi+1)/2;           // bi >= bj
    int b = blockIdx.y;
    int rA = bi*TS2, rB = bj*TS2;

    const __nv_bfloat16* hib = g_hi + (size_t)b*SS*DD;
    const __nv_bfloat16* lob = g_lo + (size_t)b*SS*DD;

    const uint32_t AH = sb, AL = sb + TILE_B, BH = sb + 2*TILE_B, BL = sb + 3*TILE_B;

    float acc[2][8][4];
    #pragma unroll
    for (int i = 0; i < 2; i++)
        #pragma unroll
        for (int j = 0; j < 8; j++)
            #pragma unroll
            for (int q = 0; q < 4; q++) acc[i][j][q] = 0.f;

    int ar = lane & 15, aseg = lane >> 4;
    int br = lane & 7, bsel = lane >> 3;
    int bnoff = (bsel >> 1) * 8, bkoff = (bsel & 1) * 8;

    int lrow = tid >> 1, lcol = (tid & 1) * 32;

    for (int c = 0; c < NCHUNK; c++) {
        int kk = c * KC;
        {
            const uint4* pAh = (const uint4*)(hib + (size_t)(rA+lrow)*DD + kk + lcol);
            const uint4* pAl = (const uint4*)(lob + (size_t)(rA+lrow)*DD + kk + lcol);
            const uint4* pBh = (const uint4*)(hib + (size_t)(rB+lrow)*DD + kk + lcol);
            const uint4* pBl = (const uint4*)(lob + (size_t)(rB+lrow)*DD + kk + lcol);
            uint32_t so = (uint32_t)(lrow*LDA + lcol) * 2;
            #pragma unroll
            for (int q = 0; q < 4; q++) {
                *(uint4*)(smem + (AH - sb) + so + q*16) = pAh[q];
                *(uint4*)(smem + (AL - sb) + so + q*16) = pAl[q];
                *(uint4*)(smem + (BH - sb) + so + q*16) = pBh[q];
                *(uint4*)(smem + (BL - sb) + so + q*16) = pBl[q];
            }
        }
        __syncthreads();

        #pragma unroll
        for (int ks = 0; ks < KC/16; ks++) {
            int kb = ks * 16;
            uint32_t ah[2][4], al[2][4];
            #pragma unroll
            for (int mt = 0; mt < 2; mt++) {
                uint32_t ao = (uint32_t)((wm*32 + mt*16 + ar)*LDA + kb + aseg*8) * 2;
                ldmx4(ah[mt], AH + ao);
                ldmx4(al[mt], AL + ao);
            }
            #pragma unroll
            for (int np = 0; np < 4; np++) {
                uint32_t bo = (uint32_t)((wn*64 + np*16 + bnoff + br)*LDA + kb + bkoff) * 2;
                uint32_t bh[4], bl[4];
                ldmx4(bh, BH + bo);
                ldmx4(bl, BL + bo);
                #pragma unroll
                for (int mt = 0; mt < 2; mt++) {
                    #pragma unroll
                    for (int sub = 0; sub < 2; sub++) {
                        int nt = np*2 + sub;
                        mma16816(acc[mt][nt], ah[mt], bh[sub*2], bh[sub*2+1]);
                        mma16816(acc[mt][nt], ah[mt], bl[sub*2], bl[sub*2+1]);
                        mma16816(acc[mt][nt], al[mt], bh[sub*2], bh[sub*2+1]);
                    }
                }
            }
        }
        __syncthreads();
    }

    float* simb = g_sim + (size_t)b*SS*SS;
    int fr = lane >> 2, fc = (lane & 3) * 2;

    #pragma unroll
    for (int mt = 0; mt < 2; mt++) {
        #pragma unroll
        for (int nt = 0; nt < 8; nt++) {
            int r0 = rA + wm*32 + mt*16 + fr;
            int cc = rB + wn*64 + nt*8 + fc;
            *(float2*)(simb + (size_t)r0*SS + cc)     = make_float2(acc[mt][nt][0], acc[mt][nt][1]);
            *(float2*)(simb + (size_t)(r0+8)*SS + cc) = make_float2(acc[mt][nt][2], acc[mt][nt][3]);
        }
    }

    if (bi != bj) {
        float* Cs = (float*)smem;   // reuse: [col][row], stride 132
        __syncthreads();
        #pragma unroll
        for (int mt = 0; mt < 2; mt++) {
            #pragma unroll
            for (int nt = 0; nt < 8; nt++) {
                int r0 = wm*32 + mt*16 + fr;
                int cc = wn*64 + nt*8 + fc;
                Cs[(cc+0)*132 + r0]   = acc[mt][nt][0];
                Cs[(cc+1)*132 + r0]   = acc[mt][nt][1];
                Cs[(cc+0)*132 + r0+8] = acc[mt][nt][2];
                Cs[(cc+1)*132 + r0+8] = acc[mt][nt][3];
            }
        }
        __syncthreads();
        for (int w = tid; w < 128*32; w += 256) {
            int n = w >> 5, m4 = (w & 31) * 4;
            float4 v = make_float4(Cs[n*132 + m4], Cs[n*132 + m4 + 1],
                                   Cs[n*132 + m4 + 2], Cs[n*132 + m4 + 3]);
            *(float4*)(simb + (size_t)(rB + n)*SS + rA + m4) = v;
        }
    }
}

// ---------------- 3. top-8 approx candidates -> exact fp32 rescore -> top-3 ----------------
__global__ void k_top3() {
    int row = blockIdx.x;
    int b = row / SS, i = row % SS;
    const float* srow = g_sim + (size_t)b*SS*SS + (size_t)i*SS;
    __shared__ float sv[SS];
    __shared__ float wmax[8];
    __shared__ int   widx[8];
    __shared__ int   cand[NCAND];
    __shared__ float ex[NCAND];
    int t = threadIdx.x;
    int lane = t & 31, wid = t >> 5;

    #pragma unroll
    for (int q = 0; q < 8; q++) {
        int idx = q*256 + t;
        sv[idx] = (idx == i) ? NEG_INF : srow[idx];
    }
    __syncthreads();

    for (int p = 0; p < NCAND; p++) {
        float bv = NEG_INF; int bidx = SS;
        #pragma unroll
        for (int q = 0; q < 8; q++) {
            int idx = q*256 + t;
            float v = sv[idx];
            if (v > bv || (v == bv && idx < bidx)) { bv = v; bidx = idx; }
        }
        #pragma unroll
        for (int o = 16; o > 0; o >>= 1) {
            float ov = __shfl_xor_sync(0xffffffffu, bv, o);
            int   oi = __shfl_xor_sync(0xffffffffu, bidx, o);
            if (ov > bv || (ov == bv && oi < bidx)) { bv = ov; bidx = oi; }
        }
        if (lane == 0) { wmax[wid] = bv; widx[wid] = bidx; }
        __syncthreads();
        if (t < 32) {
            float v2 = (t < 8) ? wmax[t] : NEG_INF;
            int   i2 = (t < 8) ? widx[t] : SS;
            #pragma unroll
            for (int o = 4; o > 0; o >>= 1) {
                float ov = __shfl_xor_sync(0xffffffffu, v2, o);
                int   oi = __shfl_xor_sync(0xffffffffu, i2, o);
                if (ov > v2 || (ov == v2 && oi < i2)) { v2 = ov; i2 = oi; }
            }
            if (t == 0) { cand[p] = i2; sv[i2] = NEG_INF; }
        }
        __syncthreads();
    }

    // exact fp32 rescore of the 8 candidates
    float xi = g_nrm[(size_t)row*DD + t];
    for (int c = 0; c < NCAND; c++) {
        int j = cand[c];
        float pr = xi * g_nrm[((size_t)b*SS + j)*DD + t];
        #pragma unroll
        for (int o = 16; o > 0; o >>= 1) pr += __shfl_xor_sync(0xffffffffu, pr, o);
        if (lane == 0) wmax[wid] = pr;
        __syncthreads();
        if (t < 32) {
            float z = (t < 8) ? wmax[t] : 0.f;
            #pragma unroll
            for (int o = 4; o > 0; o >>= 1) z += __shfl_xor_sync(0xffffffffu, z, o);
            if (t == 0) ex[c] = z;
        }
        __syncthreads();
    }

    if (t == 0) {
        bool used[NCAND] = {};
        for (int p = 0; p < 3; p++) {
            float bv = NEG_INF; int bc = -1;
            for (int c = 0; c < NCAND; c++) {
                if (used[c]) continue;
                if (bc < 0 || ex[c] > bv) { bv = ex[c]; bc = c; }
            }
            used[bc] = true;
            g_top[(size_t)row*3 + p] = cand[bc];
        }
    }
}

// ---------------- 4. adjacency bitmask ----------------
__global__ void k_zmask() {
    int t = blockIdx.x*256 + threadIdx.x;
    if (t < RR*(SS/32)) g_mask[t] = 0u;
}

__global__ void k_edges() {
    int t = blockIdx.x*256 + threadIdx.x;
    if (t >= RR*3) return;
    int row = t / 3;
    int j = g_top[t];
    int b = row / SS, i = row % SS;
    atomicOr(&g_mask[(size_t)row*(SS/32) + (j >> 5)], 1u << (j & 31));
    atomicOr(&g_mask[((size_t)b*SS + j)*(SS/32) + (i >> 5)], 1u << (i & 31));
}

// ---------------- 5. neighbor aggregation -> combined[256:512] hi/lo ----------------
__global__ void k_agg(const float* __restrict__ x) {
    int row = blockIdx.x;
    int b = row / SS, i = row % SS;
    __shared__ int   sj[128];
    __shared__ float sw[128];
    __shared__ int   cnt;
    int t = threadIdx.x;
    int lane = t & 31, wid = t >> 5;
    if (t == 0) cnt = 0;
    __syncthreads();
    if (t < SS/32) {
        unsigned w = g_mask[(size_t)row*(SS/32) + t];
        while (w) {
            int bpos = __ffs(w) - 1;
            w &= w - 1;
            int j = t*32 + bpos;
            int p = atomicAdd(&cnt, 1);
            if (p < 128) sj[p] = j;
        }
    }
    __syncthreads();
    int n = min(cnt, 128);

    // exact cosine weights: one warp per neighbor
    const float* xi = g_nrm + (size_t)row*DD;
    for (int l = wid; l < n; l += 8) {
        const float* xj = g_nrm + ((size_t)b*SS + sj[l])*DD;
        float s = 0.f;
        #pragma unroll
        for (int q = 0; q < DD/32; q++) s += xi[lane + q*32] * xj[lane + q*32];
        #pragma unroll
        for (int o = 16; o > 0; o >>= 1) s += __shfl_xor_sync(0xffffffffu, s, o);
        if (lane == 0) sw[l] = s;
    }
    __syncthreads();

    float csum = 0.f;
    for (int l = 0; l < n; l++) csum += sw[l];
    float acc = 0.f;
    for (int l = 0; l < n; l++)
        acc += sw[l] * x[((size_t)b*SS + sj[l])*DD + t];
    float mval = acc / fmaxf(csum, 1.0f);
    __nv_bfloat16 h = __float2bfloat16(mval);
    g_chi[(size_t)row*KF + DD + t] = h;
    g_clo[(size_t)row*KF + DD + t] = __float2bfloat16(mval - __bfloat162float(h));
}

// ---------------- 6. projection GEMM via bf16 HMMA 3-split + bias + residual ----------------
// grid: (RR/128)*4 blocks, tile 128x64, K=512
__global__ void __launch_bounds__(256, 2) k_out2(const float* __restrict__ x,
                                                 const float* __restrict__ bias) {
    extern __shared__ char smem[];
    uint32_t sb = smem_u32(smem);
    int tid = threadIdx.x;
    int lane = tid & 31, wid = tid >> 5;
    int wm = wid & 3, wn = wid >> 2;        // 4 x 2 warps, warp tile 32x32

    int bx = blockIdx.x;
    int rA = (bx >> 2) * 128, cB = (bx & 3) * 64;

    const uint32_t AH = sb, AL = sb + OUT_A_B, BH = sb + 2*OUT_A_B, BL = sb + 2*OUT_A_B + OUT_B_B;

    float acc[2][4][4];
    #pragma unroll
    for (int i = 0; i < 2; i++)
        #pragma unroll
        for (int j = 0; j < 4; j++)
            #pragma unroll
            for (int q = 0; q < 4; q++) acc[i][j][q] = 0.f;

    int ar = lane & 15, aseg = lane >> 4;
    int br = lane & 7, bsel = lane >> 3;
    int bnoff = (bsel >> 1) * 8, bkoff = (bsel & 1) * 8;

    int lrow = tid >> 1, lcol = (tid & 1) * 32;

    for (int c = 0; c < KF/KC; c++) {       // 8 chunks of 64
        int kk = c * KC;
        {
            const uint4* pAh = (const uint4*)(g_chi + (size_t)(rA+lrow)*KF + kk + lcol);
            const uint4* pAl = (const uint4*)(g_clo + (size_t)(rA+lrow)*KF + kk + lcol);
            uint32_t so = (uint32_t)(lrow*LDA + lcol) * 2;
            #pragma unroll
            for (int q = 0; q < 4; q++) {
                *(uint4*)(smem + (AH - sb) + so + q*16) = pAh[q];
                *(uint4*)(smem + (AL - sb) + so + q*16) = pAl[q];
            }
            if (tid < 128) {
                const uint4* pBh = (const uint4*)(g_whi + (size_t)(cB+lrow)*KF + kk + lcol);
                const uint4* pBl = (const uint4*)(g_wlo + (size_t)(cB+lrow)*KF + kk + lcol);
                #pragma unroll
                for (int q = 0; q < 4; q++) {
                    *(uint4*)(smem + (BH - sb) + so + q*16) = pBh[q];
                    *(uint4*)(smem + (BL - sb) + so + q*16) = pBl[q];
                }
            }
        }
        __syncthreads();

        #pragma unroll
        for (int ks = 0; ks < KC/16; ks++) {
            int kb = ks * 16;
            uint32_t ah[2][4], al[2][4];
            #pragma unroll
            for (int mt = 0; mt < 2; mt++) {
                uint32_t ao = (uint32_t)((wm*32 + mt*16 + ar)*LDA + kb + aseg*8) * 2;
                ldmx4(ah[mt], AH + ao);
                ldmx4(al[mt], AL + ao);
            }
            #pragma unroll
            for (int np = 0; np < 2; np++) {
                uint32_t bo = (uint32_t)((wn*32 + np*16 + bnoff + br)*LDA + kb + bkoff) * 2;
                uint32_t bh[4], bl[4];
                ldmx4(bh, BH + bo);
                ldmx4(bl, BL + bo);
                #pragma unroll
                for (int mt = 0; mt < 2; mt++) {
                    #pragma unroll
                    for (int sub = 0; sub < 2; sub++) {
                        int nt = np*2 + sub;
                        mma16816(acc[mt][nt], ah[mt], bh[sub*2], bh[sub*2+1]);
                        mma16816(acc[mt][nt], ah[mt], bl[sub*2], bl[sub*2+1]);
                        mma16816(acc[mt][nt], al[mt], bh[sub*2], bh[sub*2+1]);
                    }
                }
            }
        }
        __syncthreads();
    }

    int fr = lane >> 2, fc = (lane & 3) * 2;
    #pragma unroll
    for (int mt = 0; mt < 2; mt++) {
        #pragma unroll
        for (int nt = 0; nt < 4; nt++) {
            int r0 = rA + wm*32 + mt*16 + fr;
            int cc = cB + wn*32 + nt*8 + fc;
            g_y[(size_t)r0*DD + cc]       = x[(size_t)r0*DD + cc]       + acc[mt][nt][0] + bias[cc];
            g_y[(size_t)r0*DD + cc+1]     = x[(size_t)r0*DD + cc+1]     + acc[mt][nt][1] + bias[cc+1];
            g_y[(size_t)(r0+8)*DD + cc]   = x[(size_t)(r0+8)*DD + cc]   + acc[mt][nt][2] + bias[cc];
            g_y[(size_t)(r0+8)*DD + cc+1] = x[(size_t)(r0+8)*DD + cc+1] + acc[mt][nt][3] + bias[cc+1];
        }
    }
}

// ---------------- 7. LayerNorm ----------------
__global__ void k_ln(const float* __restrict__ gamma, const float* __restrict__ beta,
                     float* __restrict__ out) {
    int row = blockIdx.x;
    int t = threadIdx.x;
    float v = g_y[(size_t)row*DD + t];
    __shared__ float sh[8];

    float s = v;
    #pragma unroll
    for (int o = 16; o > 0; o >>= 1) s += __shfl_xor_sync(0xffffffffu, s, o);
    if ((t & 31) == 0) sh[t >> 5] = s;
    __syncthreads();
    if (t < 32) {
        float z = (t < 8) ? sh[t] : 0.f;
        #pragma unroll
        for (int o = 4; o > 0; o >>= 1) z += __shfl_xor_sync(0xffffffffu, z, o);
        if (t == 0) sh[0] = z;
    }
    __syncthreads();
    float mu = sh[0] * (1.0f/DD);
    __syncthreads();

    float d = v - mu;
    float s2 = d*d;
    #pragma unroll
    for (int o = 16; o > 0; o >>= 1) s2 += __shfl_xor_sync(0xffffffffu, s2, o);
    if ((t & 31) == 0) sh[t >> 5] = s2;
    __syncthreads();
    if (t < 32) {
        float z = (t < 8) ? sh[t] : 0.f;
        #pragma unroll
        for (int o = 4; o > 0; o >>= 1) z += __shfl_xor_sync(0xffffffffu, z, o);
        if (t == 0) sh[0] = z;
    }
    __syncthreads();
    float var = sh[0] * (1.0f/DD);

    out[(size_t)row*DD + t] = d * rsqrtf(var + 1e-5f) * gamma[t] + beta[t];
}

// ---------------- launch ----------------
extern "C" void kernel_launch(void* const* d_in, const int* in_sizes, int n_in,
                              void* d_out, int out_size) {
    const float* x     = (const float*)d_in[0];
    const float* W     = (const float*)d_in[1];
    const float* bias  = (const float*)d_in[2];
    const float* gamma = (const float*)d_in[3];
    const float* beta  = (const float*)d_in[4];
    float* out = (float*)d_out;

    cudaFuncSetAttribute(k_sim3, cudaFuncAttributeMaxDynamicSharedMemorySize, SIM_SMEM);
    cudaFuncSetAttribute(k_out2, cudaFuncAttributeMaxDynamicSharedMemorySize, OUT_SMEM);

    k_norm<<<RR, 256>>>(x);
    k_wsplit<<<(DD*KF)/256, 256>>>(W);
    k_sim3<<<dim3(TRI2, BB), 256, SIM_SMEM>>>();
    k_top3<<<RR, 256>>>();
    k_zmask<<<(RR*(SS/32) + 255)/256, 256>>>();
    k_edges<<<(RR*3 + 255)/256, 256>>>();
    k_agg<<<RR, 256>>>(x);
    k_out2<<<(RR/128)*4, 256, OUT_SMEM>>>(x, bias);
    k_ln<<<RR, 256>>>(gamma, beta, out);
}